// round 4
// baseline (speedup 1.0000x reference)
#include <cuda_runtime.h>
#include <cuda_bf16.h>
#include <math.h>
#include <stdint.h>

#define D 128
#define N_MAX 16384
#define BM 128
#define BNT 128
#define THREADS 512

// Scratch (allocation-free rule: __device__ globals)
__device__ __nv_bfloat16 g_z1b[N_MAX * D];   // pre-scaled by 2/ln2
__device__ __nv_bfloat16 g_z2b[N_MAX * D];
__device__ float g_denom[N_MAX];
__device__ float g_pos[N_MAX];

// padded smem row stride: 128 bf16 + 8 pad = 136 elems = 272 bytes
#define SROW 272
#define TILE_BYTES (128 * SROW)          // 34816
#define OFF_A 0
#define OFF_B0 TILE_BYTES
#define OFF_B1 (2 * TILE_BYTES)
#define OFF_RED (3 * TILE_BYTES)
#define SMEM_BYTES (OFF_RED + 128 * 4)

__device__ __forceinline__ uint32_t smem_u32(const void* p) {
    uint32_t a;
    asm("{ .reg .u64 t; cvta.to.shared.u64 t, %1; cvt.u32.u64 %0, t; }"
        : "=r"(a) : "l"(p));
    return a;
}

__device__ __forceinline__ float warp_sum(float v) {
    #pragma unroll
    for (int off = 16; off > 0; off >>= 1)
        v += __shfl_xor_sync(0xFFFFFFFFu, v, off);
    return v;
}

// One warp per row: fp32 normalize, exact fp32 pos, bf16 copies (z1 pre-scaled).
__global__ void norm_kernel(const float* __restrict__ z1,
                            const float* __restrict__ z2, int N) {
    int warp = (blockIdx.x * blockDim.x + threadIdx.x) >> 5;
    int lane = threadIdx.x & 31;
    if (warp >= N) return;

    const float4 a = ((const float4*)(z1 + (size_t)warp * D))[lane];
    const float4 b = ((const float4*)(z2 + (size_t)warp * D))[lane];

    float sa = a.x * a.x + a.y * a.y + a.z * a.z + a.w * a.w;
    float sb = b.x * b.x + b.y * b.y + b.z * b.z + b.w * b.w;
    sa = warp_sum(sa);
    sb = warp_sum(sb);

    float inva = 1.0f / fmaxf(sqrtf(sa), 1e-12f);
    float invb = 1.0f / fmaxf(sqrtf(sb), 1e-12f);

    float4 an = make_float4(a.x * inva, a.y * inva, a.z * inva, a.w * inva);
    float4 bn = make_float4(b.x * invb, b.y * invb, b.z * invb, b.w * invb);

    // bake exponent scale 2/ln2 into A so epilogue is a bare ex2.approx
    const float S = 2.8853900817779268f;
    __nv_bfloat162 a01 = __float22bfloat162_rn(make_float2(an.x * S, an.y * S));
    __nv_bfloat162 a23 = __float22bfloat162_rn(make_float2(an.z * S, an.w * S));
    __nv_bfloat162 b01 = __float22bfloat162_rn(make_float2(bn.x, bn.y));
    __nv_bfloat162 b23 = __float22bfloat162_rn(make_float2(bn.z, bn.w));

    uint2 pa, pb;
    pa.x = *(uint32_t*)&a01; pa.y = *(uint32_t*)&a23;
    pb.x = *(uint32_t*)&b01; pb.y = *(uint32_t*)&b23;
    ((uint2*)(g_z1b + (size_t)warp * D))[lane] = pa;
    ((uint2*)(g_z2b + (size_t)warp * D))[lane] = pb;

    float d = an.x * bn.x + an.y * bn.y + an.z * bn.z + an.w * bn.w;
    d = warp_sum(d);
    if (lane == 0) g_pos[warp] = 2.0f * d;
}

__device__ __forceinline__ void ldsm_x4(uint32_t (&r)[4], uint32_t addr) {
    asm volatile("ldmatrix.sync.aligned.m8n8.x4.shared.b16 {%0,%1,%2,%3}, [%4];"
                 : "=r"(r[0]), "=r"(r[1]), "=r"(r[2]), "=r"(r[3]) : "r"(addr));
}

__device__ __forceinline__ void mma16816(float (&c)[4], const uint32_t (&a)[4],
                                         uint32_t b0, uint32_t b1) {
    asm volatile(
        "mma.sync.aligned.m16n8k16.row.col.f32.bf16.bf16.f32 "
        "{%0,%1,%2,%3}, {%4,%5,%6,%7}, {%8,%9}, {%0,%1,%2,%3};"
        : "+f"(c[0]), "+f"(c[1]), "+f"(c[2]), "+f"(c[3])
        : "r"(a[0]), "r"(a[1]), "r"(a[2]), "r"(a[3]), "r"(b0), "r"(b1));
}

__device__ __forceinline__ void cp16(uint32_t dst, const void* src) {
    asm volatile("cp.async.cg.shared.global [%0], [%1], 16;"
                 :: "r"(dst), "l"(src) : "memory");
}

// ---------------------------------------------------------------------------
// HMMA GEMM + fused exp/rowsum. Grid = N/128 CTAs, 512 threads (16 warps 4x4).
// Warp tile 32x32. A tile persistent; B tiles cp.async double-buffered.
// ---------------------------------------------------------------------------
__global__ void __launch_bounds__(THREADS, 1)
gemm_hmma_kernel(int N) {
    extern __shared__ char smem[];
    const uint32_t sb = smem_u32(smem);
    const int tid = threadIdx.x;
    const int wid = tid >> 5;
    const int lane = tid & 31;
    const int warp_m = wid >> 2;      // 0..3
    const int warp_n = wid & 3;       // 0..3
    const int i0 = blockIdx.x * BM;
    const int ntiles = N / BNT;       // 128

    // Load A tile (128x128 bf16) into padded smem.
    {
        const uint4* A4 = (const uint4*)(g_z1b + (size_t)i0 * D);
        #pragma unroll
        for (int t = 0; t < 4; ++t) {
            int idx = tid + t * THREADS;        // 0..2047
            int r = idx >> 4, c = idx & 15;
            *(uint4*)(smem + OFF_A + r * SROW + c * 16) = A4[idx];
        }
    }

    // Prologue: B tile 0 -> buf0
    {
        const char* B = (const char*)g_z2b;
        #pragma unroll
        for (int t = 0; t < 4; ++t) {
            int idx = tid + t * THREADS;
            int r = idx >> 4, c = idx & 15;
            cp16(sb + OFF_B0 + r * SROW + c * 16, B + (size_t)r * 256 + c * 16);
        }
        asm volatile("cp.async.commit_group;" ::: "memory");
    }

    // fragment base addresses (lane-dependent, k-offset added in loop)
    const uint32_t a_base = sb + OFF_A +
        (uint32_t)(warp_m * 32 + (lane & 15)) * SROW + (uint32_t)((lane >> 4) * 16);
    const uint32_t b_lane_off =
        (uint32_t)(warp_n * 32 + (lane & 15)) * SROW + (uint32_t)((lane >> 4) * 16);

    float c[2][4][4];
    #pragma unroll
    for (int mf = 0; mf < 2; ++mf)
        #pragma unroll
        for (int nf = 0; nf < 4; ++nf)
            #pragma unroll
            for (int v = 0; v < 4; ++v) c[mf][nf][v] = 0.f;

    float rs[4] = {0.f, 0.f, 0.f, 0.f};

    for (int jt = 0; jt < ntiles; ++jt) {
        const int s = jt & 1;
        __syncthreads();  // all threads done with buf s^1 (previous compute)

        if (jt + 1 < ntiles) {
            const char* B = (const char*)(g_z2b + (size_t)(jt + 1) * BNT * D);
            uint32_t dst = sb + (s ? OFF_B0 : OFF_B1);
            #pragma unroll
            for (int t = 0; t < 4; ++t) {
                int idx = tid + t * THREADS;
                int r = idx >> 4, ch = idx & 15;
                cp16(dst + r * SROW + ch * 16, B + (size_t)r * 256 + ch * 16);
            }
            asm volatile("cp.async.commit_group;" ::: "memory");
            asm volatile("cp.async.wait_group 1;" ::: "memory");
        } else {
            asm volatile("cp.async.wait_group 0;" ::: "memory");
        }
        __syncthreads();  // buf s visible to all

        const uint32_t b_base = sb + (s ? OFF_B1 : OFF_B0) + b_lane_off;

        #pragma unroll
        for (int kk = 0; kk < 8; ++kk) {
            const uint32_t koff = (uint32_t)kk * 32;
            uint32_t a[2][4];
            #pragma unroll
            for (int mf = 0; mf < 2; ++mf)
                ldsm_x4(a[mf], a_base + (uint32_t)(mf * 16) * SROW + koff);
            uint32_t bm[2][4];
            #pragma unroll
            for (int nf2 = 0; nf2 < 2; ++nf2)
                ldsm_x4(bm[nf2], b_base + (uint32_t)(nf2 * 16) * SROW + koff);

            #pragma unroll
            for (int mf = 0; mf < 2; ++mf)
                #pragma unroll
                for (int nf = 0; nf < 4; ++nf)
                    mma16816(c[mf][nf], a[mf],
                             bm[nf >> 1][nf & 1], bm[nf >> 1][(nf & 1) + 2]);
        }

        // fused epilogue: rowsum += 2^c  (exponent scale pre-baked into A)
        #pragma unroll
        for (int mf = 0; mf < 2; ++mf) {
            float lo = 0.f, hi = 0.f;
            #pragma unroll
            for (int nf = 0; nf < 4; ++nf) {
                float e0, e1, e2, e3;
                asm("ex2.approx.f32 %0, %1;" : "=f"(e0) : "f"(c[mf][nf][0]));
                asm("ex2.approx.f32 %0, %1;" : "=f"(e1) : "f"(c[mf][nf][1]));
                asm("ex2.approx.f32 %0, %1;" : "=f"(e2) : "f"(c[mf][nf][2]));
                asm("ex2.approx.f32 %0, %1;" : "=f"(e3) : "f"(c[mf][nf][3]));
                lo += e0 + e1;
                hi += e2 + e3;
                c[mf][nf][0] = 0.f; c[mf][nf][1] = 0.f;
                c[mf][nf][2] = 0.f; c[mf][nf][3] = 0.f;
            }
            rs[mf * 2 + 0] += lo;
            rs[mf * 2 + 1] += hi;
        }
    }

    // reduce rs across the 4 lanes of each quad (same row group)
    #pragma unroll
    for (int i = 0; i < 4; ++i) {
        rs[i] += __shfl_xor_sync(0xFFFFFFFFu, rs[i], 1);
        rs[i] += __shfl_xor_sync(0xFFFFFFFFu, rs[i], 2);
    }

    float* red = (float*)(smem + OFF_RED);
    __syncthreads();
    if (tid < 128) red[tid] = 0.f;
    __syncthreads();
    if ((lane & 3) == 0) {
        #pragma unroll
        for (int mf = 0; mf < 2; ++mf) {
            #pragma unroll
            for (int sub = 0; sub < 2; ++sub) {
                int row = warp_m * 32 + mf * 16 + sub * 8 + (lane >> 2);
                atomicAdd(&red[row], rs[mf * 2 + sub]);
            }
        }
    }
    __syncthreads();
    if (tid < 128) g_denom[i0 + tid] = red[tid];
}

__global__ void loss_kernel(float* __restrict__ out, int N) {
    __shared__ float smr[256];
    float s = 0.f;
    for (int i = threadIdx.x; i < N; i += 256)
        s += logf(g_denom[i] + 1e-8f) - g_pos[i];
    smr[threadIdx.x] = s;
    __syncthreads();
    #pragma unroll
    for (int off = 128; off > 0; off >>= 1) {
        if (threadIdx.x < off) smr[threadIdx.x] += smr[threadIdx.x + off];
        __syncthreads();
    }
    if (threadIdx.x == 0) out[0] = smr[0] / (float)N;
}

extern "C" void kernel_launch(void* const* d_in, const int* in_sizes, int n_in,
                              void* d_out, int out_size) {
    const float* z1 = (const float*)d_in[0];
    const float* z2 = (const float*)d_in[1];
    float* out = (float*)d_out;
    const int N = in_sizes[0] / D;  // 16384

    cudaFuncSetAttribute(gemm_hmma_kernel,
                         cudaFuncAttributeMaxDynamicSharedMemorySize,
                         (int)SMEM_BYTES);

    norm_kernel<<<(N + 7) / 8, 256>>>(z1, z2, N);
    gemm_hmma_kernel<<<N / BM, THREADS, SMEM_BYTES>>>(N);
    loss_kernel<<<1, 256>>>(out, N);
}

// round 5
// speedup vs baseline: 1.0041x; 1.0041x over previous
#include <cuda_runtime.h>
#include <cuda_bf16.h>
#include <cuda_fp8.h>
#include <math.h>
#include <stdint.h>

#define D 128
#define N_MAX 16384
#define BM 128
#define BNT 128
#define THREADS 512

// Scratch (allocation-free rule: __device__ globals)
__device__ uint8_t g_z1f8[N_MAX * D];   // e4m3, pre-scaled by 2/ln2
__device__ uint8_t g_z2f8[N_MAX * D];   // e4m3
__device__ float g_denom[N_MAX];
__device__ float g_pos[N_MAX];

// padded smem row stride: 128 fp8 + 16 pad = 144 bytes
#define SROW 144
#define TILE_BYTES (128 * SROW)          // 18432
#define OFF_A 0
#define OFF_B0 TILE_BYTES
#define OFF_B1 (2 * TILE_BYTES)
#define OFF_RED (3 * TILE_BYTES)
#define SMEM_BYTES (OFF_RED + 128 * 4)

__device__ __forceinline__ uint32_t smem_u32(const void* p) {
    uint32_t a;
    asm("{ .reg .u64 t; cvta.to.shared.u64 t, %1; cvt.u32.u64 %0, t; }"
        : "=r"(a) : "l"(p));
    return a;
}

__device__ __forceinline__ float warp_sum(float v) {
    #pragma unroll
    for (int off = 16; off > 0; off >>= 1)
        v += __shfl_xor_sync(0xFFFFFFFFu, v, off);
    return v;
}

// One warp per row: fp32 normalize, exact fp32 pos, e4m3 copies (z1 pre-scaled).
__global__ void norm_kernel(const float* __restrict__ z1,
                            const float* __restrict__ z2, int N) {
    int warp = (blockIdx.x * blockDim.x + threadIdx.x) >> 5;
    int lane = threadIdx.x & 31;
    if (warp >= N) return;

    const float4 a = ((const float4*)(z1 + (size_t)warp * D))[lane];
    const float4 b = ((const float4*)(z2 + (size_t)warp * D))[lane];

    float sa = a.x * a.x + a.y * a.y + a.z * a.z + a.w * a.w;
    float sb = b.x * b.x + b.y * b.y + b.z * b.z + b.w * b.w;
    sa = warp_sum(sa);
    sb = warp_sum(sb);

    float inva = 1.0f / fmaxf(sqrtf(sa), 1e-12f);
    float invb = 1.0f / fmaxf(sqrtf(sb), 1e-12f);

    float4 an = make_float4(a.x * inva, a.y * inva, a.z * inva, a.w * inva);
    float4 bn = make_float4(b.x * invb, b.y * invb, b.z * invb, b.w * invb);

    // bake exponent scale 2/ln2 into A so epilogue is a bare ex2.approx
    const float S = 2.8853900817779268f;
    __nv_fp8x2_storage_t a01 = __nv_cvt_float2_to_fp8x2(
        make_float2(an.x * S, an.y * S), __NV_SATFINITE, __NV_E4M3);
    __nv_fp8x2_storage_t a23 = __nv_cvt_float2_to_fp8x2(
        make_float2(an.z * S, an.w * S), __NV_SATFINITE, __NV_E4M3);
    __nv_fp8x2_storage_t b01 = __nv_cvt_float2_to_fp8x2(
        make_float2(bn.x, bn.y), __NV_SATFINITE, __NV_E4M3);
    __nv_fp8x2_storage_t b23 = __nv_cvt_float2_to_fp8x2(
        make_float2(bn.z, bn.w), __NV_SATFINITE, __NV_E4M3);

    uint32_t pa = (uint32_t)a01 | ((uint32_t)a23 << 16);
    uint32_t pb = (uint32_t)b01 | ((uint32_t)b23 << 16);
    ((uint32_t*)(g_z1f8 + (size_t)warp * D))[lane] = pa;
    ((uint32_t*)(g_z2f8 + (size_t)warp * D))[lane] = pb;

    float d = an.x * bn.x + an.y * bn.y + an.z * bn.z + an.w * bn.w;
    d = warp_sum(d);
    if (lane == 0) g_pos[warp] = 2.0f * d;
}

__device__ __forceinline__ void ldsm_x4(uint32_t (&r)[4], uint32_t addr) {
    asm volatile("ldmatrix.sync.aligned.m8n8.x4.shared.b16 {%0,%1,%2,%3}, [%4];"
                 : "=r"(r[0]), "=r"(r[1]), "=r"(r[2]), "=r"(r[3]) : "r"(addr));
}

__device__ __forceinline__ void mma16832(float (&c)[4], const uint32_t (&a)[4],
                                         uint32_t b0, uint32_t b1) {
    asm volatile(
        "mma.sync.aligned.m16n8k32.row.col.f32.e4m3.e4m3.f32 "
        "{%0,%1,%2,%3}, {%4,%5,%6,%7}, {%8,%9}, {%0,%1,%2,%3};"
        : "+f"(c[0]), "+f"(c[1]), "+f"(c[2]), "+f"(c[3])
        : "r"(a[0]), "r"(a[1]), "r"(a[2]), "r"(a[3]), "r"(b0), "r"(b1));
}

__device__ __forceinline__ void cp16(uint32_t dst, const void* src) {
    asm volatile("cp.async.cg.shared.global [%0], [%1], 16;"
                 :: "r"(dst), "l"(src) : "memory");
}

// ---------------------------------------------------------------------------
// FP8 QMMA GEMM + fused exp/rowsum. Grid = N/128 CTAs, 512 threads (16 warps).
// Warp tile 32x32, m16n8k32 e4m3. A persistent; B cp.async double-buffered.
// ---------------------------------------------------------------------------
__global__ void __launch_bounds__(THREADS, 1)
gemm_fp8_kernel(int N) {
    extern __shared__ char smem[];
    const uint32_t sb = smem_u32(smem);
    const int tid = threadIdx.x;
    const int wid = tid >> 5;
    const int lane = tid & 31;
    const int warp_m = wid >> 2;      // 0..3
    const int warp_n = wid & 3;       // 0..3
    const int i0 = blockIdx.x * BM;
    const int ntiles = N / BNT;       // 128

    // Load A tile (128 rows x 128 fp8) into padded smem.
    {
        const uint4* A4 = (const uint4*)(g_z1f8 + (size_t)i0 * D);
        #pragma unroll
        for (int t = 0; t < 2; ++t) {
            int idx = tid + t * THREADS;        // 0..1023
            int r = idx >> 3, c = idx & 7;
            *(uint4*)(smem + OFF_A + r * SROW + c * 16) = A4[idx];
        }
    }

    // Prologue: B tile 0 -> buf0
    {
        const char* B = (const char*)g_z2f8;
        #pragma unroll
        for (int t = 0; t < 2; ++t) {
            int idx = tid + t * THREADS;
            int r = idx >> 3, c = idx & 7;
            cp16(sb + OFF_B0 + r * SROW + c * 16, B + (size_t)r * 128 + c * 16);
        }
        asm volatile("cp.async.commit_group;" ::: "memory");
    }

    // fragment base addresses: 16 rows x 2 sixteen-byte column halves per x4
    const uint32_t a_base = sb + OFF_A +
        (uint32_t)(warp_m * 32 + (lane & 15)) * SROW + (uint32_t)((lane >> 4) * 16);
    const uint32_t b_lane_off =
        (uint32_t)(warp_n * 32 + (lane & 15)) * SROW + (uint32_t)((lane >> 4) * 16);

    float c[2][4][4];
    #pragma unroll
    for (int mf = 0; mf < 2; ++mf)
        #pragma unroll
        for (int nf = 0; nf < 4; ++nf)
            #pragma unroll
            for (int v = 0; v < 4; ++v) c[mf][nf][v] = 0.f;

    float rs[4] = {0.f, 0.f, 0.f, 0.f};

    for (int jt = 0; jt < ntiles; ++jt) {
        const int s = jt & 1;
        __syncthreads();  // all threads done with buf s^1 (previous compute)

        if (jt + 1 < ntiles) {
            const char* B = (const char*)(g_z2f8 + (size_t)(jt + 1) * BNT * D);
            uint32_t dst = sb + (s ? OFF_B0 : OFF_B1);
            #pragma unroll
            for (int t = 0; t < 2; ++t) {
                int idx = tid + t * THREADS;
                int r = idx >> 3, ch = idx & 7;
                cp16(dst + r * SROW + ch * 16, B + (size_t)r * 128 + ch * 16);
            }
            asm volatile("cp.async.commit_group;" ::: "memory");
            asm volatile("cp.async.wait_group 1;" ::: "memory");
        } else {
            asm volatile("cp.async.wait_group 0;" ::: "memory");
        }
        __syncthreads();  // buf s visible to all

        const uint32_t b_base = sb + (s ? OFF_B1 : OFF_B0) + b_lane_off;

        #pragma unroll
        for (int kk = 0; kk < 4; ++kk) {          // K=128 / k32 = 4 steps
            const uint32_t koff = (uint32_t)kk * 32;
            uint32_t a[2][4];
            #pragma unroll
            for (int mf = 0; mf < 2; ++mf)
                ldsm_x4(a[mf], a_base + (uint32_t)(mf * 16) * SROW + koff);
            uint32_t bm[2][4];
            #pragma unroll
            for (int nf2 = 0; nf2 < 2; ++nf2)
                ldsm_x4(bm[nf2], b_base + (uint32_t)(nf2 * 16) * SROW + koff);

            #pragma unroll
            for (int mf = 0; mf < 2; ++mf)
                #pragma unroll
                for (int nf = 0; nf < 4; ++nf)
                    mma16832(c[mf][nf], a[mf],
                             bm[nf >> 1][nf & 1], bm[nf >> 1][(nf & 1) + 2]);
        }

        // fused epilogue: rowsum += 2^c  (exponent scale pre-baked into A)
        #pragma unroll
        for (int mf = 0; mf < 2; ++mf) {
            float lo = 0.f, hi = 0.f;
            #pragma unroll
            for (int nf = 0; nf < 4; ++nf) {
                float e0, e1, e2, e3;
                asm("ex2.approx.f32 %0, %1;" : "=f"(e0) : "f"(c[mf][nf][0]));
                asm("ex2.approx.f32 %0, %1;" : "=f"(e1) : "f"(c[mf][nf][1]));
                asm("ex2.approx.f32 %0, %1;" : "=f"(e2) : "f"(c[mf][nf][2]));
                asm("ex2.approx.f32 %0, %1;" : "=f"(e3) : "f"(c[mf][nf][3]));
                lo += e0 + e1;
                hi += e2 + e3;
                c[mf][nf][0] = 0.f; c[mf][nf][1] = 0.f;
                c[mf][nf][2] = 0.f; c[mf][nf][3] = 0.f;
            }
            rs[mf * 2 + 0] += lo;
            rs[mf * 2 + 1] += hi;
        }
    }

    // reduce rs across the 4 lanes of each quad (same row group)
    #pragma unroll
    for (int i = 0; i < 4; ++i) {
        rs[i] += __shfl_xor_sync(0xFFFFFFFFu, rs[i], 1);
        rs[i] += __shfl_xor_sync(0xFFFFFFFFu, rs[i], 2);
    }

    float* red = (float*)(smem + OFF_RED);
    __syncthreads();
    if (tid < 128) red[tid] = 0.f;
    __syncthreads();
    if ((lane & 3) == 0) {
        #pragma unroll
        for (int mf = 0; mf < 2; ++mf) {
            #pragma unroll
            for (int sub = 0; sub < 2; ++sub) {
                int row = warp_m * 32 + mf * 16 + sub * 8 + (lane >> 2);
                atomicAdd(&red[row], rs[mf * 2 + sub]);
            }
        }
    }
    __syncthreads();
    if (tid < 128) g_denom[i0 + tid] = red[tid];
}

__global__ void loss_kernel(float* __restrict__ out, int N) {
    __shared__ float smr[256];
    float s = 0.f;
    for (int i = threadIdx.x; i < N; i += 256)
        s += logf(g_denom[i] + 1e-8f) - g_pos[i];
    smr[threadIdx.x] = s;
    __syncthreads();
    #pragma unroll
    for (int off = 128; off > 0; off >>= 1) {
        if (threadIdx.x < off) smr[threadIdx.x] += smr[threadIdx.x + off];
        __syncthreads();
    }
    if (threadIdx.x == 0) out[0] = smr[0] / (float)N;
}

extern "C" void kernel_launch(void* const* d_in, const int* in_sizes, int n_in,
                              void* d_out, int out_size) {
    const float* z1 = (const float*)d_in[0];
    const float* z2 = (const float*)d_in[1];
    float* out = (float*)d_out;
    const int N = in_sizes[0] / D;  // 16384

    cudaFuncSetAttribute(gemm_fp8_kernel,
                         cudaFuncAttributeMaxDynamicSharedMemorySize,
                         (int)SMEM_BYTES);

    norm_kernel<<<(N + 7) / 8, 256>>>(z1, z2, N);
    gemm_fp8_kernel<<<N / BM, THREADS, SMEM_BYTES>>>(N);
    loss_kernel<<<1, 256>>>(out, N);
}